// round 16
// baseline (speedup 1.0000x reference)
#include <cuda_runtime.h>

#define BB    64
#define LPROG 25
#define IMG2  (64*196)      // ic-pair words per image state plane
typedef unsigned long long ull;

// ---------------- device scratch (no allocs allowed) ----------------
__device__ unsigned g_V_H [BB*IMG2], g_V_L [BB*IMG2];
__device__ unsigned g_OUT_H[BB*IMG2], g_OUT_L[BB*IMG2];
__device__ unsigned g_SAV_H[BB*IMG2], g_SAV_L[BB*IMG2];
__device__ unsigned g_X_H [BB*IMG2], g_X_L [BB*IMG2];
__device__ unsigned g_H_H [BB*IMG2], g_H_L [BB*IMG2];
__device__ unsigned g_F_H [BB*512*196], g_F_L [BB*512*196];   // packed stem input
__device__ float g_FLAT[BB*25088];
__device__ float g_FC1[BB*1024];

// pre-split weights, plane-split: [H: bank,icp,tap,oc][L: same]  (R9-proven layout)
#define STEM1_N (512*9*128)
#define UW_N    (11*64*9*128)
#define BW_N    (6*64*9*128)
#define STEM2_N (64*9*128)
#define BWP_N   (6*128*128)
__device__ unsigned g_stem1t[2*STEM1_N];
__device__ unsigned g_stem2t[2*STEM2_N];
__device__ unsigned g_uw1t[2*UW_N];
__device__ unsigned g_uw2t[2*UW_N];
__device__ unsigned g_bw1t[2*BW_N];
__device__ unsigned g_bw2t[2*BW_N];
__device__ unsigned g_bwpt[2*BWP_N];
__device__ float g_clst[128*512];

// ---------------- f32x2 helpers (cls section) ----------------
__device__ __forceinline__ ull pack2(float lo, float hi){
    ull r; asm("mov.b64 %0, {%1, %2};" : "=l"(r) : "f"(lo), "f"(hi)); return r;
}
__device__ __forceinline__ void fma2(ull &d, ull a, ull b){
    asm("fma.rn.f32x2 %0, %1, %2, %0;" : "+l"(d) : "l"(a), "l"(b));
}
__device__ __forceinline__ void unpack2(ull v, float &lo, float &hi){
    asm("mov.b64 {%0, %1}, %2;" : "=f"(lo), "=f"(hi) : "l"(v));
}

// ---------------- bf16 split helpers ----------------
__device__ __forceinline__ unsigned packbf(float v0, float v1){
    unsigned r; asm("cvt.rn.bf16x2.f32 %0, %1, %2;" : "=r"(r) : "f"(v1), "f"(v0));
    return r;
}
__device__ __forceinline__ uint2 split2u(float v0, float v1){
    uint2 r;
    r.x = packbf(v0, v1);
    float h0 = __uint_as_float(r.x << 16);
    float h1 = __uint_as_float(r.x & 0xFFFF0000u);
    r.y = packbf(v0 - h0, v1 - h1);
    return r;
}
__device__ __forceinline__ void split2(float v0, float v1, unsigned &hi, unsigned &lo){
    uint2 r = split2u(v0, v1); hi = r.x; lo = r.y;
}
__device__ __forceinline__ float lo_val2(unsigned h, unsigned l){
    return __uint_as_float(h << 16) + __uint_as_float(l << 16);
}
__device__ __forceinline__ float hi_val2(unsigned h, unsigned l){
    return __uint_as_float(h & 0xFFFF0000u) + __uint_as_float(l & 0xFFFF0000u);
}
__device__ __forceinline__ void mma16816(float c[4], const unsigned a[4],
                                         unsigned b0, unsigned b1){
    asm volatile("mma.sync.aligned.m16n8k16.row.col.f32.bf16.bf16.f32 "
        "{%0,%1,%2,%3}, {%4,%5,%6,%7}, {%8,%9}, {%0,%1,%2,%3};"
        : "+f"(c[0]), "+f"(c[1]), "+f"(c[2]), "+f"(c[3])
        : "r"(a[0]), "r"(a[1]), "r"(a[2]), "r"(a[3]), "r"(b0), "r"(b1));
}

// ---------------- cp.async helpers ----------------
__device__ __forceinline__ void cpa4(unsigned smaddr, const void* gptr, unsigned bytes){
    asm volatile("cp.async.ca.shared.global [%0], [%1], 4, %2;"
                 :: "r"(smaddr), "l"(gptr), "r"(bytes));
}
__device__ __forceinline__ void cpa_commit(){ asm volatile("cp.async.commit_group;"); }
__device__ __forceinline__ void cpa_wait0(){ asm volatile("cp.async.wait_group 0;" ::: "memory"); }

// ------- transpose+split: src [nb][OC][IC][KK] f32 -> dst planes [nb][ICP][KK][OC] -------
__device__ __forceinline__ void trs_core(const float* __restrict__ src, unsigned* __restrict__ dst,
                                         int nb, int OC, int IC, int KK){
    int ICP = IC >> 1;
    int total = nb*ICP*KK*OC;
    for (int i = blockIdx.x*blockDim.x + threadIdx.x; i < total; i += gridDim.x*blockDim.x){
        int oc = i % OC;
        int r  = i / OC;
        int k  = r % KK; r /= KK;
        int icp = r % ICP;
        int bank = r / ICP;
        const float* s = src + ((ull)(bank*OC + oc)*IC + 2*icp)*KK + k;
        uint2 v = split2u(s[0], s[KK]);
        dst[i] = v.x;
        dst[total + i] = v.y;
    }
}
__device__ __forceinline__ void tr_core(const float* __restrict__ src, float* __restrict__ dst,
                                        int nb, int OC, int IC, int KK){
    int total = nb*OC*IC*KK;
    for (int i = blockIdx.x*blockDim.x + threadIdx.x; i < total; i += gridDim.x*blockDim.x){
        int oc = i % OC;
        int r  = i / OC;
        int k  = r % KK; r /= KK;
        int ic = r % IC;
        int bank = r / IC;
        dst[i] = src[((bank*OC + oc)*IC + ic)*KK + k];
    }
}
__device__ __forceinline__ void packF_core(const float* __restrict__ feats, int b0){
    int total = 32*512*196;
    for (int i = blockIdx.x*blockDim.x + threadIdx.x; i < total; i += gridDim.x*blockDim.x){
        int pos = i % 196;
        int r   = i / 196;
        int icp = r % 512;
        int b   = b0 + r / 512;
        const float* s = feats + ((ull)b*1024 + 2*icp)*196 + pos;
        uint2 v = split2u(s[0], s[196]);
        ull idx = (ull)b*512*196 + (ull)icp*196 + pos;
        g_F_H[idx] = v.x; g_F_L[idx] = v.y;
    }
}
// 3 pre-launches so program_kernel stays at the captured launch position
__global__ void tr1(const float* a, const float* b, const float* feats){
    trs_core(a, g_stem1t, 1, 128, 1024, 9);
    trs_core(b, g_uw1t, 11, 128, 128, 9);
    packF_core(feats, 0);
}
__global__ void tr2(const float* a, const float* b, const float* c, const float* feats){
    trs_core(a, g_uw2t, 11, 128, 128, 9);
    trs_core(b, g_bw1t,  6, 128, 128, 9);
    trs_core(c, g_bw2t,  6, 128, 128, 9);
    packF_core(feats, 32);
}
__global__ void tr3(const float* a, const float* b, const float* c){
    trs_core(a, g_stem2t, 1, 128, 128, 9);
    trs_core(b, g_bwpt,   6, 128, 256, 1);
    tr_core (c, g_clst,   1, 512, 128, 1);
    for (int i = blockIdx.x*blockDim.x + threadIdx.x; i < BB*1024; i += gridDim.x*blockDim.x)
        g_FC1[i] = 0.f;
}

// ---------------- dynamic smem buffer layout (words) — R9-proven ----------------
#define CV_INL   2112
#define CV_WH    4224
#define CV_WL    7104
#define CV_BUF   9984
#define PJ_INL   1856
#define PJ_WH    3712
#define PJ_WL    4032
#define PJ_BUF   4352
#define DYN_SMEM (2*CV_BUF*4)    // 79,872 bytes

// cluster-wide phase boundary (R15-proven: cluster-scope fence)
__device__ __forceinline__ void csync(){
    asm volatile("fence.acq_rel.cluster;" ::: "memory");
    asm volatile("barrier.cluster.arrive.aligned;" ::: "memory");
    asm volatile("barrier.cluster.wait.aligned;"   ::: "memory");
}

// zero the write-invariant halo cells of BOTH conv buffers (both planes).
// Interior staging never touches these cells, so they stay zero until a
// proj_mma reuses the smem with a different layout (then re-zero).
__device__ __forceinline__ void zero_halo(unsigned* dynsm, int t){
    for (int i = t; i < 2048; i += 256){
        int icp = i >> 8, cell = i & 255, yy = cell >> 4, xx = cell & 15;
        if (yy == 0 || yy == 15 || xx == 0 || xx == 15){
            dynsm[icp*264 + cell] = 0u;
            dynsm[CV_INL + icp*264 + cell] = 0u;
            dynsm[CV_BUF + icp*264 + cell] = 0u;
            dynsm[CV_BUF + CV_INL + icp*264 + cell] = 0u;
        }
    }
}

// ---------------- conv staging via cp.async: INTERIOR CELLS ONLY ----------------
__device__ __forceinline__ void conv_stage(unsigned smbase,
        const unsigned* __restrict__ srcH, const unsigned* __restrict__ srcL,
        const unsigned* __restrict__ wtH,  const unsigned* __restrict__ wtL,
        int icp0, int oc0, int t)
{
#pragma unroll
    for (int e = 0; e < 7; e++){
        int i = t + e*256;
        if (i < 1568){
            int icp = i / 196, pos = i - icp*196;
            int y = pos / 14, x = pos - y*14;
            unsigned sa = smbase + (icp*264 + (y+1)*16 + (x+1))*4;
            int gidx = (icp0+icp)*196 + pos;
            cpa4(sa,             srcH + gidx, 4u);
            cpa4(sa + CV_INL*4,  srcL + gidx, 4u);
        }
    }
#pragma unroll
    for (int e = 0; e < 9; e++){
        int i = t + e*256;
        int oc = i & 31, r = i >> 5, tap = r % 9, icp = r / 9;
        int gw = ((icp0+icp)*9 + tap)*128 + oc0 + oc;
        unsigned sa = smbase + (CV_WH + icp*360 + tap*40 + oc)*4;
        cpa4(sa,                     wtH + gw, 4u);
        cpa4(sa + (CV_WL-CV_WH)*4,   wtL + gw, 4u);
    }
}

// ---------------- 3x3 conv slice via bf16-split tensor cores (pipelined) ----------------
__device__ void conv3x3_mma(unsigned* dynsm,
        const unsigned* __restrict__ srcH, const unsigned* __restrict__ srcL,
        const unsigned* __restrict__ wtH,  const unsigned* __restrict__ wtL,
        int oc0, const float* __restrict__ bias,
        const unsigned* residH, const unsigned* residL,
        unsigned* dstH, unsigned* dstL,
        unsigned* dst2H, unsigned* dst2L,
        unsigned* dst3H, unsigned* dst3L, int ICP)
{
    const int t = threadIdx.x;
    const int lane = t & 31, wid = t >> 5;
    const int mh = wid >> 2, nw = wid & 3;
    const int gr = lane >> 2, ct = lane & 3;
    const unsigned smbase = (unsigned)__cvta_generic_to_shared(dynsm);
    float acc[7][4] = {};
    int cb[7];
#pragma unroll
    for (int tt = 0; tt < 7; tt++){
        int p = nw*56 + tt*8 + gr;
        if (p < 196){ int y = p/14, x = p - y*14; cb[tt] = y*16 + x; }
        else cb[tt] = -1;
    }

    const int nch = ICP >> 3;
    conv_stage(smbase, srcH, srcL, wtH, wtL, 0, oc0, t);
    cpa_commit();
    for (int c = 0; c < nch; c++){
        cpa_wait0();
        __syncthreads();
        if (c + 1 < nch){
            conv_stage(smbase + ((c+1)&1)*CV_BUF*4, srcH, srcL, wtH, wtL,
                       (c+1)*8, oc0, t);
            cpa_commit();
        }
        unsigned* bb  = dynsm + (c&1)*CV_BUF;
        unsigned* inH = bb;
        unsigned* inL = bb + CV_INL;
        unsigned* wH  = bb + CV_WH;
        unsigned* wL  = bb + CV_WL;
#pragma unroll 1
        for (int tap = 0; tap < 9; tap++){
            const int toff = (tap/3)*16 + (tap - (tap/3)*3);
            unsigned aH[4], aL[4];
            const int wb = tap*40 + 16*mh + gr;
            aH[0] = wH[ct*360 + wb];      aH[1] = wH[ct*360 + wb + 8];
            aH[2] = wH[(ct+4)*360 + wb];  aH[3] = wH[(ct+4)*360 + wb + 8];
            aL[0] = wL[ct*360 + wb];      aL[1] = wL[ct*360 + wb + 8];
            aL[2] = wL[(ct+4)*360 + wb];  aL[3] = wL[(ct+4)*360 + wb + 8];
#pragma unroll
            for (int tt = 0; tt < 7; tt++){
                int w = (cb[tt] >= 0) ? cb[tt] + toff : 15;
                unsigned bH0 = inH[ct*264 + w];
                unsigned bH1 = inH[(ct+4)*264 + w];
                unsigned bL0 = inL[ct*264 + w];
                unsigned bL1 = inL[(ct+4)*264 + w];
                mma16816(acc[tt], aH, bH0, bH1);
                mma16816(acc[tt], aH, bL0, bL1);
                mma16816(acc[tt], aL, bH0, bH1);
            }
        }
        // no bottom barrier: next iteration's wait0+syncthreads protects buffer reuse
    }
    // epilogue: bias (+residual) + relu; pack ic-pairs via xor-4 shuffle; store planes
    const int ocA = oc0 + 16*mh + gr, ocB = ocA + 8;
    const float bA = bias[ocA], bB = bias[ocB];
    const bool evenGr = ((gr & 1) == 0);
    const int iA = (ocA >> 1)*196, iB = (ocB >> 1)*196;
#pragma unroll
    for (int tt = 0; tt < 7; tt++){
        int p0 = nw*56 + tt*8 + 2*ct, p1 = p0 + 1;
        float v00 = acc[tt][0] + bA, v01 = acc[tt][1] + bA;
        float v10 = acc[tt][2] + bB, v11 = acc[tt][3] + bB;
        if (residH){
            if (p0 < 196){
                v00 += evenGr ? lo_val2(residH[iA+p0], residL[iA+p0])
                              : hi_val2(residH[iA+p0], residL[iA+p0]);
                v10 += evenGr ? lo_val2(residH[iB+p0], residL[iB+p0])
                              : hi_val2(residH[iB+p0], residL[iB+p0]);
            }
            if (p1 < 196){
                v01 += evenGr ? lo_val2(residH[iA+p1], residL[iA+p1])
                              : hi_val2(residH[iA+p1], residL[iA+p1]);
                v11 += evenGr ? lo_val2(residH[iB+p1], residL[iB+p1])
                              : hi_val2(residH[iB+p1], residL[iB+p1]);
            }
        }
        v00 = fmaxf(v00,0.f); v01 = fmaxf(v01,0.f);
        v10 = fmaxf(v10,0.f); v11 = fmaxf(v11,0.f);
        float u00 = __shfl_xor_sync(0xffffffffu, v00, 4);
        float u01 = __shfl_xor_sync(0xffffffffu, v01, 4);
        float u10 = __shfl_xor_sync(0xffffffffu, v10, 4);
        float u11 = __shfl_xor_sync(0xffffffffu, v11, 4);
        if (evenGr){
            if (p0 < 196){
                uint2 wA = split2u(v00, u00), wB = split2u(v10, u10);
                dstH[iA+p0] = wA.x; dstL[iA+p0] = wA.y;
                dstH[iB+p0] = wB.x; dstL[iB+p0] = wB.y;
                if (dst2H){ dst2H[iA+p0]=wA.x; dst2L[iA+p0]=wA.y;
                            dst2H[iB+p0]=wB.x; dst2L[iB+p0]=wB.y; }
                if (dst3H){ dst3H[iA+p0]=wA.x; dst3L[iA+p0]=wA.y;
                            dst3H[iB+p0]=wB.x; dst3L[iB+p0]=wB.y; }
            }
            if (p1 < 196){
                uint2 wA = split2u(v01, u01), wB = split2u(v11, u11);
                dstH[iA+p1] = wA.x; dstL[iA+p1] = wA.y;
                dstH[iB+p1] = wB.x; dstL[iB+p1] = wB.y;
                if (dst2H){ dst2H[iA+p1]=wA.x; dst2L[iA+p1]=wA.y;
                            dst2H[iB+p1]=wB.x; dst2L[iB+p1]=wB.y; }
                if (dst3H){ dst3H[iA+p1]=wA.x; dst3L[iA+p1]=wA.y;
                            dst3H[iB+p1]=wB.x; dst3L[iB+p1]=wB.y; }
            }
        }
    }
}

// ---------------- proj staging via cp.async (R9-proven) ----------------
__device__ __forceinline__ void proj_stage(unsigned smbase,
        const unsigned* __restrict__ AH, const unsigned* __restrict__ AL,
        const unsigned* __restrict__ SH, const unsigned* __restrict__ SL,
        const unsigned* __restrict__ wtH, const unsigned* __restrict__ wtL,
        int icp0, int oc0, int t)
{
#pragma unroll
    for (int e = 0; e < 7; e++){
        int i = t + e*256;
        int icp = i / 224, pos = i - icp*224;
        int icg = icp0 + icp;
        bool ok = (pos < 196);
        const unsigned* sH = (icg < 64) ? AH + icg*196 : SH + (icg-64)*196;
        const unsigned* sL = (icg < 64) ? AL + icg*196 : SL + (icg-64)*196;
        int gidx = ok ? pos : 0;
        unsigned nb = ok ? 4u : 0u;
        unsigned sa = smbase + (icp*232 + pos)*4;
        cpa4(sa,            sH + gidx, nb);
        cpa4(sa + PJ_INL*4, sL + gidx, nb);
    }
    {
        int oc = t & 31, icp = t >> 5;
        int gw = (icp0 + icp)*128 + oc0 + oc;
        unsigned sa = smbase + (PJ_WH + icp*40 + oc)*4;
        cpa4(sa,                   wtH + gw, 4u);
        cpa4(sa + (PJ_WL-PJ_WH)*4, wtL + gw, 4u);
    }
}

// ---------------- binary 1x1 projection via bf16-split tensor cores (R9) -----------------
__device__ void proj_mma(unsigned* dynsm,
        const unsigned* __restrict__ AH, const unsigned* __restrict__ AL,
        const unsigned* __restrict__ SH, const unsigned* __restrict__ SL,
        const unsigned* __restrict__ wtH, const unsigned* __restrict__ wtL,
        int oc0, const float* __restrict__ bias,
        unsigned* dstH, unsigned* dstL)
{
    const int t = threadIdx.x;
    const int lane = t & 31, wid = t >> 5;
    const int mh = wid >> 2, nw = wid & 3;
    const int gr = lane >> 2, ct = lane & 3;
    const unsigned smbase = (unsigned)__cvta_generic_to_shared(dynsm);
    float acc[7][4] = {};

    proj_stage(smbase, AH, AL, SH, SL, wtH, wtL, 0, oc0, t);
    cpa_commit();
    for (int c = 0; c < 16; c++){
        cpa_wait0();
        __syncthreads();
        if (c + 1 < 16){
            proj_stage(smbase + ((c+1)&1)*PJ_BUF*4, AH, AL, SH, SL, wtH, wtL,
                       (c+1)*8, oc0, t);
            cpa_commit();
        }
        unsigned* bb  = dynsm + (c&1)*PJ_BUF;
        unsigned* inH = bb;
        unsigned* inL = bb + PJ_INL;
        unsigned* wH  = bb + PJ_WH;
        unsigned* wL  = bb + PJ_WL;
        unsigned aH[4], aL[4];
        aH[0] = wH[ct*40 + 16*mh + gr];      aH[1] = wH[ct*40 + 16*mh + gr + 8];
        aH[2] = wH[(ct+4)*40 + 16*mh + gr];  aH[3] = wH[(ct+4)*40 + 16*mh + gr + 8];
        aL[0] = wL[ct*40 + 16*mh + gr];      aL[1] = wL[ct*40 + 16*mh + gr + 8];
        aL[2] = wL[(ct+4)*40 + 16*mh + gr];  aL[3] = wL[(ct+4)*40 + 16*mh + gr + 8];
#pragma unroll
        for (int tt = 0; tt < 7; tt++){
            int w = nw*56 + tt*8 + gr;
            unsigned bH0 = inH[ct*232 + w];
            unsigned bH1 = inH[(ct+4)*232 + w];
            unsigned bL0 = inL[ct*232 + w];
            unsigned bL1 = inL[(ct+4)*232 + w];
            mma16816(acc[tt], aH, bH0, bH1);
            mma16816(acc[tt], aH, bL0, bL1);
            mma16816(acc[tt], aL, bH0, bH1);
        }
        // no bottom barrier: next iteration's wait0+syncthreads protects buffer reuse
    }
    const int ocA = oc0 + 16*mh + gr, ocB = ocA + 8;
    const float bA = bias[ocA], bB = bias[ocB];
    const bool evenGr = ((gr & 1) == 0);
    const int iA = (ocA >> 1)*196, iB = (ocB >> 1)*196;
#pragma unroll
    for (int tt = 0; tt < 7; tt++){
        int p0 = nw*56 + tt*8 + 2*ct, p1 = p0 + 1;
        float v00 = fmaxf(acc[tt][0] + bA, 0.f);
        float v01 = fmaxf(acc[tt][1] + bA, 0.f);
        float v10 = fmaxf(acc[tt][2] + bB, 0.f);
        float v11 = fmaxf(acc[tt][3] + bB, 0.f);
        float u00 = __shfl_xor_sync(0xffffffffu, v00, 4);
        float u01 = __shfl_xor_sync(0xffffffffu, v01, 4);
        float u10 = __shfl_xor_sync(0xffffffffu, v10, 4);
        float u11 = __shfl_xor_sync(0xffffffffu, v11, 4);
        if (evenGr){
            if (p0 < 196){
                uint2 wA = split2u(v00, u00), wB = split2u(v10, u10);
                dstH[iA+p0] = wA.x; dstL[iA+p0] = wA.y;
                dstH[iB+p0] = wB.x; dstL[iB+p0] = wB.y;
            }
            if (p1 < 196){
                uint2 wA = split2u(v01, u01), wB = split2u(v11, u11);
                dstH[iA+p1] = wA.x; dstL[iA+p1] = wA.y;
                dstH[iB+p1] = wB.x; dstL[iB+p1] = wB.y;
            }
        }
    }
}

// ---------------- persistent program kernel: 64 images x 4-CTA clusters ----------------
__global__ void __cluster_dims__(4,1,1) __launch_bounds__(256, 2)
program_kernel(const int* __restrict__ programs,
               const float* __restrict__ stem_b1, const float* __restrict__ stem_b2,
               const float* __restrict__ ub1, const float* __restrict__ ub2,
               const float* __restrict__ bbp, const float* __restrict__ bb1,
               const float* __restrict__ bb2, const float* __restrict__ cls_b)
{
    extern __shared__ unsigned dynsm[];
    const int cta = blockIdx.x;
    const int b   = cta >> 2;
    const int oc0 = (cta & 3) * 32;
    unsigned *OUTH = g_OUT_H + b*IMG2, *OUTL = g_OUT_L + b*IMG2;
    unsigned *SAVH = g_SAV_H + b*IMG2, *SAVL = g_SAV_L + b*IMG2;
    unsigned *XH   = g_X_H   + b*IMG2, *XL   = g_X_L   + b*IMG2;
    unsigned *HH   = g_H_H   + b*IMG2, *HL   = g_H_L   + b*IMG2;
    unsigned *VH   = g_V_H   + b*IMG2, *VL   = g_V_L   + b*IMG2;

    // one-time halo zero (interior staging never overwrites halo cells)
    zero_halo(dynsm, threadIdx.x);

    // stem
    conv3x3_mma(dynsm, g_F_H + (ull)b*512*196, g_F_L + (ull)b*512*196,
                g_stem1t, g_stem1t + STEM1_N, oc0, stem_b1,
                nullptr, nullptr, HH, HL, nullptr, nullptr, nullptr, nullptr, 512);
    csync();
    conv3x3_mma(dynsm, HH, HL, g_stem2t, g_stem2t + STEM2_N, oc0, stem_b2,
                nullptr, nullptr, VH, VL, OUTH, OUTL, SAVH, SAVL, 64);
    csync();

    // program walk (reverse token order)
    for (int tpos = LPROG-1; tpos >= 0; tpos--){
        int tok = programs[b*LPROG + tpos];
        if (tok < 4) continue;
        if (tok >= 15){                          // binary module
            int pi = tok - 15;
            proj_mma(dynsm, OUTH, OUTL, SAVH, SAVL,
                     g_bwpt + pi*128*128, g_bwpt + BWP_N + pi*128*128,
                     oc0, bbp + pi*128, XH, XL);
            __syncthreads();                     // proj readers done before halo re-zero
            zero_halo(dynsm, threadIdx.x);       // proj reused smem: restore conv halo
            csync();
            conv3x3_mma(dynsm, XH, XL,
                        g_bw1t + pi*(64*9*128), g_bw1t + BW_N + pi*(64*9*128),
                        oc0, bb1 + pi*128, nullptr, nullptr,
                        HH, HL, nullptr, nullptr, nullptr, nullptr, 64);
            csync();
            conv3x3_mma(dynsm, HH, HL,
                        g_bw2t + pi*(64*9*128), g_bw2t + BW_N + pi*(64*9*128),
                        oc0, bb2 + pi*128, XH, XL,
                        OUTH, OUTL, nullptr, nullptr, nullptr, nullptr, 64);
            csync();
        } else {                                 // scene (4) or unary (5..14)
            int pi = (tok == 4) ? 0 : tok - 4;
            const unsigned* srcH = (tok == 4) ? VH : OUTH;
            const unsigned* srcL = (tok == 4) ? VL : OUTL;
            if (tok == 4){
                for (int i = threadIdx.x; i < 16*196; i += 256){
                    int idx = (oc0 >> 1)*196 + i;
                    SAVH[idx] = OUTH[idx]; SAVL[idx] = OUTL[idx];
                }
            }
            conv3x3_mma(dynsm, srcH, srcL,
                        g_uw1t + pi*(64*9*128), g_uw1t + UW_N + pi*(64*9*128),
                        oc0, ub1 + pi*128, nullptr, nullptr,
                        HH, HL, nullptr, nullptr, nullptr, nullptr, 64);
            csync();
            conv3x3_mma(dynsm, HH, HL,
                        g_uw2t + pi*(64*9*128), g_uw2t + UW_N + pi*(64*9*128),
                        oc0, ub2 + pi*128, srcH, srcL,
                        OUTH, OUTL, nullptr, nullptr, nullptr, nullptr, 64);
            csync();
        }
    }

    // ----- fused classifier: this CTA computes cls oc [ (cta&3)*128 , +128 ) -----
    {
        float* s_in = (float*)dynsm;            // [16][196]
        float* s_w  = s_in + 3136;              // [16][32]
        float* s_c  = s_w + 512;                // [32][196]
        const int t = threadIdx.x;
        const int p0 = t, p1 = t + 98;
        const bool active = (t < 98);
        const int C0 = (cta & 3)*128;

        for (int g = 0; g < 4; g++){
            int oc0c = C0 + g*32;
            ull acc0[16], acc1[16];
#pragma unroll
            for (int j = 0; j < 16; j++){ acc0[j] = 0ull; acc1[j] = 0ull; }
            for (int icg = 0; icg < 8; icg++){
                __syncthreads();
                for (int i = t; i < 8*196; i += 256){
                    int icp = i/196, p = i - icp*196;
                    unsigned vh = OUTH[(icg*8 + icp)*196 + p];
                    unsigned vl = OUTL[(icg*8 + icp)*196 + p];
                    s_in[(2*icp)*196 + p]   = lo_val2(vh, vl);
                    s_in[(2*icp+1)*196 + p] = hi_val2(vh, vl);
                }
                for (int i = t; i < 512; i += 256){
                    int oc = i & 31, ic = i >> 5;
                    s_w[ic*32 + oc] = g_clst[(icg*16 + ic)*512 + oc0c + oc];
                }
                __syncthreads();
                if (active){
#pragma unroll 4
                    for (int ic = 0; ic < 16; ic++){
                        float av = s_in[ic*196 + p0], bv = s_in[ic*196 + p1];
                        ull ap = pack2(av, av), bp = pack2(bv, bv);
#pragma unroll
                        for (int gg = 0; gg < 8; gg++){
                            ulonglong2 w2 = *reinterpret_cast<const ulonglong2*>(&s_w[ic*32 + gg*4]);
                            fma2(acc0[2*gg  ], ap, w2.x);
                            fma2(acc0[2*gg+1], ap, w2.y);
                            fma2(acc1[2*gg  ], bp, w2.x);
                            fma2(acc1[2*gg+1], bp, w2.y);
                        }
                    }
                }
            }
            __syncthreads();
            if (active){
#pragma unroll
                for (int j = 0; j < 16; j++){
                    int oc = oc0c + 2*j;
                    float a0, a1, c0, c1;
                    unpack2(acc0[j], a0, a1);
                    unpack2(acc1[j], c0, c1);
                    float bz0 = cls_b[oc], bz1 = cls_b[oc+1];
                    s_c[(2*j  )*196 + p0] = fmaxf(a0+bz0, 0.f);
                    s_c[(2*j+1)*196 + p0] = fmaxf(a1+bz1, 0.f);
                    s_c[(2*j  )*196 + p1] = fmaxf(c0+bz0, 0.f);
                    s_c[(2*j+1)*196 + p1] = fmaxf(c1+bz1, 0.f);
                }
            }
            __syncthreads();
            for (int i = t; i < 32*49; i += 256){
                int ocl = i/49, cell = i - ocl*49;
                int py = cell/7, px = cell - py*7;
                int base = 28*py + 2*px;
                float m = fmaxf(fmaxf(s_c[ocl*196 + base], s_c[ocl*196 + base+1]),
                                fmaxf(s_c[ocl*196 + base+14], s_c[ocl*196 + base+15]));
                g_FLAT[b*25088 + (oc0c + ocl)*49 + cell] = m;
            }
        }
    }
}

// ---------------- fc1 via bf16-split tensor cores ----------------
__global__ void fc1_kernel(const float* __restrict__ w){
    const int n0 = blockIdx.x*64;
    const int k0 = blockIdx.y*1568;
    __shared__ unsigned sAh[16][72], sAl[16][72], sBh[16][72], sBl[16][72];
    const int t = threadIdx.x;
    const int lane = t & 31, wid = t >> 5;
    const int gr = lane >> 2, ct = lane & 3;
    const int mt = wid >> 1, nh = wid & 1;
    float acc[4][4] = {};

    for (int kk = 0; kk < 1568; kk += 32){
        __syncthreads();
        for (int i = t; i < 1024; i += 256){
            int kp = i & 15, m = i >> 4;
            const float* a = g_FLAT + m*25088 + k0 + kk + 2*kp;
            unsigned h, l; split2(a[0], a[1], h, l);
            sAh[kp][m] = h; sAl[kp][m] = l;
            const float* bptr = w + (ull)(n0 + m)*25088 + k0 + kk + 2*kp;
            split2(bptr[0], bptr[1], h, l);
            sBh[kp][m] = h; sBl[kp][m] = l;
        }
        __syncthreads();
#pragma unroll
        for (int ks = 0; ks < 2; ks++){
            const int kp0 = ks*8;
            unsigned aH[4], aL[4];
            aH[0] = sAh[kp0+ct][mt*16+gr];     aH[1] = sAh[kp0+ct][mt*16+gr+8];
            aH[2] = sAh[kp0+ct+4][mt*16+gr];   aH[3] = sAh[kp0+ct+4][mt*16+gr+8];
            aL[0] = sAl[kp0+ct][mt*16+gr];     aL[1] = sAl[kp0+ct][mt*16+gr+8];
            aL[2] = sAl[kp0+ct+4][mt*16+gr];   aL[3] = sAl[kp0+ct+4][mt*16+gr+8];
#pragma unroll
            for (int tile = 0; tile < 4; tile++){
                int n = nh*32 + tile*8 + gr;
                unsigned bH0 = sBh[kp0+ct][n],   bH1 = sBh[kp0+ct+4][n];
                unsigned bL0 = sBl[kp0+ct][n],   bL1 = sBl[kp0+ct+4][n];
                mma16816(acc[tile], aH, bH0, bH1);
                mma16816(acc[tile], aH, bL0, bL1);
                mma16816(acc[tile], aL, bH0, bH1);
            }
        }
    }
#pragma unroll
    for (int tile = 0; tile < 4; tile++){
        int m = mt*16 + gr;
        int n = n0 + nh*32 + tile*8 + 2*ct;
        atomicAdd(&g_FC1[m*1024 + n],       acc[tile][0]);
        atomicAdd(&g_FC1[m*1024 + n + 1],   acc[tile][1]);
        atomicAdd(&g_FC1[(m+8)*1024 + n],   acc[tile][2]);
        atomicAdd(&g_FC1[(m+8)*1024 + n+1], acc[tile][3]);
    }
}

// ---------------- fc2 ----------------
__global__ void fc2_kernel(const float* __restrict__ fc1_b, const float* __restrict__ w2,
                           const float* __restrict__ b2, float* __restrict__ out){
    int b = blockIdx.x;
    const int t = threadIdx.x;
    int n2 = t >> 3, kl = t & 7;
    float acc = 0.f;
    for (int k = kl; k < 1024; k += 8)
        acc += fmaxf(g_FC1[b*1024 + k] + fc1_b[k], 0.f) * w2[n2*1024 + k];
    __shared__ float red[256];
    red[t] = acc;
    __syncthreads();
    if (kl == 0){
        float s = red[t];
#pragma unroll
        for (int q = 1; q < 8; q++) s += red[t+q];
        out[b*32 + n2] = s + b2[n2];
    }
}

// ---------------- launch ----------------
extern "C" void kernel_launch(void* const* d_in, const int* in_sizes, int n_in,
                              void* d_out, int out_size){
    const float* feats    = (const float*)d_in[0];
    const int*   programs = (const int*)  d_in[1];
    const float* stem_w1  = (const float*)d_in[2];
    const float* stem_b1  = (const float*)d_in[3];
    const float* stem_w2  = (const float*)d_in[4];
    const float* stem_b2  = (const float*)d_in[5];
    const float* uw1      = (const float*)d_in[6];
    const float* ub1      = (const float*)d_in[7];
    const float* uw2      = (const float*)d_in[8];
    const float* ub2      = (const float*)d_in[9];
    const float* bwp      = (const float*)d_in[10];
    const float* bbp      = (const float*)d_in[11];
    const float* bw1      = (const float*)d_in[12];
    const float* bb1      = (const float*)d_in[13];
    const float* bw2      = (const float*)d_in[14];
    const float* bb2      = (const float*)d_in[15];
    const float* cls_w    = (const float*)d_in[16];
    const float* cls_b    = (const float*)d_in[17];
    const float* fc1_w    = (const float*)d_in[18];
    const float* fc1_b    = (const float*)d_in[19];
    const float* fc2_w    = (const float*)d_in[20];
    const float* fc2_b    = (const float*)d_in[21];
    float* out = (float*)d_out;

    static bool attr_set = false;
    if (!attr_set){
        cudaFuncSetAttribute(program_kernel,
                             cudaFuncAttributeMaxDynamicSharedMemorySize, DYN_SMEM);
        attr_set = true;
    }

    tr1<<<1024, 256>>>(stem_w1, uw1, feats);
    tr2<<<1024, 256>>>(uw2, bw1, bw2, feats);
    tr3<<<512,  256>>>(stem_w2, bwp, cls_w);

    program_kernel<<<BB*4, 256, DYN_SMEM>>>(programs, stem_b1, stem_b2,
                                            ub1, ub2, bbp, bb1, bb2, cls_b);

    fc1_kernel<<<dim3(16, 16), 256>>>(fc1_w);
    fc2_kernel<<<BB, 256>>>(fc1_b, fc2_w, fc2_b, out);
}

// round 17
// speedup vs baseline: 1.0215x; 1.0215x over previous
#include <cuda_runtime.h>

#define BB    64
#define LPROG 25
#define IMG2  (64*196)      // ic-pair words per image state plane
typedef unsigned long long ull;

// ---------------- device scratch (no allocs allowed) ----------------
__device__ unsigned g_V_H [BB*IMG2], g_V_L [BB*IMG2];
__device__ unsigned g_OUT_H[BB*IMG2], g_OUT_L[BB*IMG2];
__device__ unsigned g_SAV_H[BB*IMG2], g_SAV_L[BB*IMG2];
__device__ unsigned g_X_H [BB*IMG2], g_X_L [BB*IMG2];
__device__ unsigned g_H_H [BB*IMG2], g_H_L [BB*IMG2];
__device__ unsigned g_F_H [BB*512*196], g_F_L [BB*512*196];   // packed stem input
__device__ float g_FLAT[BB*25088];
__device__ float g_FC1[BB*1024];

// pre-split weights, plane-split: [H: bank,icp,tap,oc][L: same]  (R9-proven layout)
#define STEM1_N (512*9*128)
#define UW_N    (11*64*9*128)
#define BW_N    (6*64*9*128)
#define STEM2_N (64*9*128)
#define BWP_N   (6*128*128)
__device__ unsigned g_stem1t[2*STEM1_N];
__device__ unsigned g_stem2t[2*STEM2_N];
__device__ unsigned g_uw1t[2*UW_N];
__device__ unsigned g_uw2t[2*UW_N];
__device__ unsigned g_bw1t[2*BW_N];
__device__ unsigned g_bw2t[2*BW_N];
__device__ unsigned g_bwpt[2*BWP_N];
__device__ float g_clst[128*512];

// ---------------- f32x2 helpers (cls section) ----------------
__device__ __forceinline__ ull pack2(float lo, float hi){
    ull r; asm("mov.b64 %0, {%1, %2};" : "=l"(r) : "f"(lo), "f"(hi)); return r;
}
__device__ __forceinline__ void fma2(ull &d, ull a, ull b){
    asm("fma.rn.f32x2 %0, %1, %2, %0;" : "+l"(d) : "l"(a), "l"(b));
}
__device__ __forceinline__ void unpack2(ull v, float &lo, float &hi){
    asm("mov.b64 {%0, %1}, %2;" : "=f"(lo), "=f"(hi) : "l"(v));
}

// ---------------- bf16 split helpers ----------------
__device__ __forceinline__ unsigned packbf(float v0, float v1){
    unsigned r; asm("cvt.rn.bf16x2.f32 %0, %1, %2;" : "=r"(r) : "f"(v1), "f"(v0));
    return r;
}
__device__ __forceinline__ uint2 split2u(float v0, float v1){
    uint2 r;
    r.x = packbf(v0, v1);
    float h0 = __uint_as_float(r.x << 16);
    float h1 = __uint_as_float(r.x & 0xFFFF0000u);
    r.y = packbf(v0 - h0, v1 - h1);
    return r;
}
__device__ __forceinline__ void split2(float v0, float v1, unsigned &hi, unsigned &lo){
    uint2 r = split2u(v0, v1); hi = r.x; lo = r.y;
}
__device__ __forceinline__ float lo_val2(unsigned h, unsigned l){
    return __uint_as_float(h << 16) + __uint_as_float(l << 16);
}
__device__ __forceinline__ float hi_val2(unsigned h, unsigned l){
    return __uint_as_float(h & 0xFFFF0000u) + __uint_as_float(l & 0xFFFF0000u);
}
__device__ __forceinline__ void mma16816(float c[4], const unsigned a[4],
                                         unsigned b0, unsigned b1){
    asm volatile("mma.sync.aligned.m16n8k16.row.col.f32.bf16.bf16.f32 "
        "{%0,%1,%2,%3}, {%4,%5,%6,%7}, {%8,%9}, {%0,%1,%2,%3};"
        : "+f"(c[0]), "+f"(c[1]), "+f"(c[2]), "+f"(c[3])
        : "r"(a[0]), "r"(a[1]), "r"(a[2]), "r"(a[3]), "r"(b0), "r"(b1));
}

// ---------------- cp.async helpers ----------------
__device__ __forceinline__ void cpa4(unsigned smaddr, const void* gptr, unsigned bytes){
    asm volatile("cp.async.ca.shared.global [%0], [%1], 4, %2;"
                 :: "r"(smaddr), "l"(gptr), "r"(bytes));
}
__device__ __forceinline__ void cpa_commit(){ asm volatile("cp.async.commit_group;"); }
__device__ __forceinline__ void cpa_wait0(){ asm volatile("cp.async.wait_group 0;" ::: "memory"); }

// ------- transpose+split: src [nb][OC][IC][KK] f32 -> dst planes [nb][ICP][KK][OC] -------
__device__ __forceinline__ void trs_core(const float* __restrict__ src, unsigned* __restrict__ dst,
                                         int nb, int OC, int IC, int KK){
    int ICP = IC >> 1;
    int total = nb*ICP*KK*OC;
    for (int i = blockIdx.x*blockDim.x + threadIdx.x; i < total; i += gridDim.x*blockDim.x){
        int oc = i % OC;
        int r  = i / OC;
        int k  = r % KK; r /= KK;
        int icp = r % ICP;
        int bank = r / ICP;
        const float* s = src + ((ull)(bank*OC + oc)*IC + 2*icp)*KK + k;
        uint2 v = split2u(s[0], s[KK]);
        dst[i] = v.x;
        dst[total + i] = v.y;
    }
}
__device__ __forceinline__ void tr_core(const float* __restrict__ src, float* __restrict__ dst,
                                        int nb, int OC, int IC, int KK){
    int total = nb*OC*IC*KK;
    for (int i = blockIdx.x*blockDim.x + threadIdx.x; i < total; i += gridDim.x*blockDim.x){
        int oc = i % OC;
        int r  = i / OC;
        int k  = r % KK; r /= KK;
        int ic = r % IC;
        int bank = r / IC;
        dst[i] = src[((bank*OC + oc)*IC + ic)*KK + k];
    }
}
__device__ __forceinline__ void packF_core(const float* __restrict__ feats, int b0){
    int total = 32*512*196;
    for (int i = blockIdx.x*blockDim.x + threadIdx.x; i < total; i += gridDim.x*blockDim.x){
        int pos = i % 196;
        int r   = i / 196;
        int icp = r % 512;
        int b   = b0 + r / 512;
        const float* s = feats + ((ull)b*1024 + 2*icp)*196 + pos;
        uint2 v = split2u(s[0], s[196]);
        ull idx = (ull)b*512*196 + (ull)icp*196 + pos;
        g_F_H[idx] = v.x; g_F_L[idx] = v.y;
    }
}
// 3 pre-launches so program_kernel stays at the captured launch position
__global__ void tr1(const float* a, const float* b, const float* feats){
    trs_core(a, g_stem1t, 1, 128, 1024, 9);
    trs_core(b, g_uw1t, 11, 128, 128, 9);
    packF_core(feats, 0);
}
__global__ void tr2(const float* a, const float* b, const float* c, const float* feats){
    trs_core(a, g_uw2t, 11, 128, 128, 9);
    trs_core(b, g_bw1t,  6, 128, 128, 9);
    trs_core(c, g_bw2t,  6, 128, 128, 9);
    packF_core(feats, 32);
}
__global__ void tr3(const float* a, const float* b, const float* c){
    trs_core(a, g_stem2t, 1, 128, 128, 9);
    trs_core(b, g_bwpt,   6, 128, 256, 1);
    tr_core (c, g_clst,   1, 512, 128, 1);
    for (int i = blockIdx.x*blockDim.x + threadIdx.x; i < BB*1024; i += gridDim.x*blockDim.x)
        g_FC1[i] = 0.f;
}

// ---------------- dynamic smem buffer layout (words) — R9-proven ----------------
#define CV_INL   2112
#define CV_WH    4224
#define CV_WL    7104
#define CV_BUF   9984
#define PJ_INL   1856
#define PJ_WH    3712
#define PJ_WL    4032
#define PJ_BUF   4352
#define DYN_SMEM (2*CV_BUF*4)    // 79,872 bytes

// cluster-wide phase boundary (R15-proven: cluster-scope fence)
__device__ __forceinline__ void csync(){
    asm volatile("fence.acq_rel.cluster;" ::: "memory");
    asm volatile("barrier.cluster.arrive.aligned;" ::: "memory");
    asm volatile("barrier.cluster.wait.aligned;"   ::: "memory");
}

// ---------------- conv staging via cp.async (R9-proven) ----------------
__device__ __forceinline__ void conv_stage(unsigned smbase,
        const unsigned* __restrict__ srcH, const unsigned* __restrict__ srcL,
        const unsigned* __restrict__ wtH,  const unsigned* __restrict__ wtL,
        int icp0, int oc0, int t)
{
#pragma unroll
    for (int e = 0; e < 8; e++){
        int i = t + e*256;
        int icp = i >> 8, cell = i & 255, yy = cell >> 4, xx = cell & 15;
        bool ok = (yy >= 1 && yy <= 14 && xx >= 1 && xx <= 14);
        int gidx = ok ? (icp0+icp)*196 + (yy-1)*14 + (xx-1) : 0;
        unsigned nb = ok ? 4u : 0u;
        unsigned sa = smbase + (icp*264 + cell)*4;
        cpa4(sa,             srcH + gidx, nb);
        cpa4(sa + CV_INL*4,  srcL + gidx, nb);
    }
#pragma unroll
    for (int e = 0; e < 9; e++){
        int i = t + e*256;
        int oc = i & 31, r = i >> 5, tap = r % 9, icp = r / 9;
        int gw = ((icp0+icp)*9 + tap)*128 + oc0 + oc;
        unsigned sa = smbase + (CV_WH + icp*360 + tap*40 + oc)*4;
        cpa4(sa,                     wtH + gw, 4u);
        cpa4(sa + (CV_WL-CV_WH)*4,   wtL + gw, 4u);
    }
}

// ---------------- 3x3 conv slice via bf16-split tensor cores (pipelined) ----------------
__device__ void conv3x3_mma(unsigned* dynsm,
        const unsigned* __restrict__ srcH, const unsigned* __restrict__ srcL,
        const unsigned* __restrict__ wtH,  const unsigned* __restrict__ wtL,
        int oc0, const float* __restrict__ bias,
        const unsigned* residH, const unsigned* residL,
        unsigned* dstH, unsigned* dstL,
        unsigned* dst2H, unsigned* dst2L,
        unsigned* dst3H, unsigned* dst3L, int ICP)
{
    const int t = threadIdx.x;
    const int lane = t & 31, wid = t >> 5;
    const int mh = wid >> 2, nw = wid & 3;
    const int gr = lane >> 2, ct = lane & 3;
    const unsigned smbase = (unsigned)__cvta_generic_to_shared(dynsm);
    float acc[7][4] = {};
    int cb[7];
#pragma unroll
    for (int tt = 0; tt < 7; tt++){
        int p = nw*56 + tt*8 + gr;
        if (p < 196){ int y = p/14, x = p - y*14; cb[tt] = y*16 + x; }
        else cb[tt] = -1;
    }

    const int nch = ICP >> 3;
    conv_stage(smbase, srcH, srcL, wtH, wtL, 0, oc0, t);
    cpa_commit();
    for (int c = 0; c < nch; c++){
        cpa_wait0();
        __syncthreads();
        if (c + 1 < nch){
            conv_stage(smbase + ((c+1)&1)*CV_BUF*4, srcH, srcL, wtH, wtL,
                       (c+1)*8, oc0, t);
            cpa_commit();
        }
        unsigned* bb  = dynsm + (c&1)*CV_BUF;
        unsigned* inH = bb;
        unsigned* inL = bb + CV_INL;
        unsigned* wH  = bb + CV_WH;
        unsigned* wL  = bb + CV_WL;
#pragma unroll 1
        for (int tap = 0; tap < 9; tap++){
            const int toff = (tap/3)*16 + (tap - (tap/3)*3);
            unsigned aH[4], aL[4];
            const int wb = tap*40 + 16*mh + gr;
            aH[0] = wH[ct*360 + wb];      aH[1] = wH[ct*360 + wb + 8];
            aH[2] = wH[(ct+4)*360 + wb];  aH[3] = wH[(ct+4)*360 + wb + 8];
            aL[0] = wL[ct*360 + wb];      aL[1] = wL[ct*360 + wb + 8];
            aL[2] = wL[(ct+4)*360 + wb];  aL[3] = wL[(ct+4)*360 + wb + 8];
#pragma unroll
            for (int tt = 0; tt < 7; tt++){
                int w = (cb[tt] >= 0) ? cb[tt] + toff : 15;
                unsigned bH0 = inH[ct*264 + w];
                unsigned bH1 = inH[(ct+4)*264 + w];
                unsigned bL0 = inL[ct*264 + w];
                unsigned bL1 = inL[(ct+4)*264 + w];
                mma16816(acc[tt], aH, bH0, bH1);
                mma16816(acc[tt], aH, bL0, bL1);
                mma16816(acc[tt], aL, bH0, bH1);
            }
        }
        // no bottom barrier: next iteration's wait0+syncthreads protects buffer reuse
    }
    // epilogue: bias (+residual) + relu; pack ic-pairs via xor-4 shuffle; store planes
    const int ocA = oc0 + 16*mh + gr, ocB = ocA + 8;
    const float bA = bias[ocA], bB = bias[ocB];
    const bool evenGr = ((gr & 1) == 0);
    const int iA = (ocA >> 1)*196, iB = (ocB >> 1)*196;
#pragma unroll
    for (int tt = 0; tt < 7; tt++){
        int p0 = nw*56 + tt*8 + 2*ct, p1 = p0 + 1;
        float v00 = acc[tt][0] + bA, v01 = acc[tt][1] + bA;
        float v10 = acc[tt][2] + bB, v11 = acc[tt][3] + bB;
        if (residH){
            if (p0 < 196){
                v00 += evenGr ? lo_val2(residH[iA+p0], residL[iA+p0])
                              : hi_val2(residH[iA+p0], residL[iA+p0]);
                v10 += evenGr ? lo_val2(residH[iB+p0], residL[iB+p0])
                              : hi_val2(residH[iB+p0], residL[iB+p0]);
            }
            if (p1 < 196){
                v01 += evenGr ? lo_val2(residH[iA+p1], residL[iA+p1])
                              : hi_val2(residH[iA+p1], residL[iA+p1]);
                v11 += evenGr ? lo_val2(residH[iB+p1], residL[iB+p1])
                              : hi_val2(residH[iB+p1], residL[iB+p1]);
            }
        }
        v00 = fmaxf(v00,0.f); v01 = fmaxf(v01,0.f);
        v10 = fmaxf(v10,0.f); v11 = fmaxf(v11,0.f);
        float u00 = __shfl_xor_sync(0xffffffffu, v00, 4);
        float u01 = __shfl_xor_sync(0xffffffffu, v01, 4);
        float u10 = __shfl_xor_sync(0xffffffffu, v10, 4);
        float u11 = __shfl_xor_sync(0xffffffffu, v11, 4);
        if (evenGr){
            if (p0 < 196){
                uint2 wA = split2u(v00, u00), wB = split2u(v10, u10);
                dstH[iA+p0] = wA.x; dstL[iA+p0] = wA.y;
                dstH[iB+p0] = wB.x; dstL[iB+p0] = wB.y;
                if (dst2H){ dst2H[iA+p0]=wA.x; dst2L[iA+p0]=wA.y;
                            dst2H[iB+p0]=wB.x; dst2L[iB+p0]=wB.y; }
                if (dst3H){ dst3H[iA+p0]=wA.x; dst3L[iA+p0]=wA.y;
                            dst3H[iB+p0]=wB.x; dst3L[iB+p0]=wB.y; }
            }
            if (p1 < 196){
                uint2 wA = split2u(v01, u01), wB = split2u(v11, u11);
                dstH[iA+p1] = wA.x; dstL[iA+p1] = wA.y;
                dstH[iB+p1] = wB.x; dstL[iB+p1] = wB.y;
                if (dst2H){ dst2H[iA+p1]=wA.x; dst2L[iA+p1]=wA.y;
                            dst2H[iB+p1]=wB.x; dst2L[iB+p1]=wB.y; }
                if (dst3H){ dst3H[iA+p1]=wA.x; dst3L[iA+p1]=wA.y;
                            dst3H[iB+p1]=wB.x; dst3L[iB+p1]=wB.y; }
            }
        }
    }
}

// ---------------- proj staging via cp.async (R9-proven) ----------------
__device__ __forceinline__ void proj_stage(unsigned smbase,
        const unsigned* __restrict__ AH, const unsigned* __restrict__ AL,
        const unsigned* __restrict__ SH, const unsigned* __restrict__ SL,
        const unsigned* __restrict__ wtH, const unsigned* __restrict__ wtL,
        int icp0, int oc0, int t)
{
#pragma unroll
    for (int e = 0; e < 7; e++){
        int i = t + e*256;
        int icp = i / 224, pos = i - icp*224;
        int icg = icp0 + icp;
        bool ok = (pos < 196);
        const unsigned* sH = (icg < 64) ? AH + icg*196 : SH + (icg-64)*196;
        const unsigned* sL = (icg < 64) ? AL + icg*196 : SL + (icg-64)*196;
        int gidx = ok ? pos : 0;
        unsigned nb = ok ? 4u : 0u;
        unsigned sa = smbase + (icp*232 + pos)*4;
        cpa4(sa,            sH + gidx, nb);
        cpa4(sa + PJ_INL*4, sL + gidx, nb);
    }
    {
        int oc = t & 31, icp = t >> 5;
        int gw = (icp0 + icp)*128 + oc0 + oc;
        unsigned sa = smbase + (PJ_WH + icp*40 + oc)*4;
        cpa4(sa,                   wtH + gw, 4u);
        cpa4(sa + (PJ_WL-PJ_WH)*4, wtL + gw, 4u);
    }
}

// ---------------- binary 1x1 projection via bf16-split tensor cores (R9) -----------------
__device__ void proj_mma(unsigned* dynsm,
        const unsigned* __restrict__ AH, const unsigned* __restrict__ AL,
        const unsigned* __restrict__ SH, const unsigned* __restrict__ SL,
        const unsigned* __restrict__ wtH, const unsigned* __restrict__ wtL,
        int oc0, const float* __restrict__ bias,
        unsigned* dstH, unsigned* dstL)
{
    const int t = threadIdx.x;
    const int lane = t & 31, wid = t >> 5;
    const int mh = wid >> 2, nw = wid & 3;
    const int gr = lane >> 2, ct = lane & 3;
    const unsigned smbase = (unsigned)__cvta_generic_to_shared(dynsm);
    float acc[7][4] = {};

    proj_stage(smbase, AH, AL, SH, SL, wtH, wtL, 0, oc0, t);
    cpa_commit();
    for (int c = 0; c < 16; c++){
        cpa_wait0();
        __syncthreads();
        if (c + 1 < 16){
            proj_stage(smbase + ((c+1)&1)*PJ_BUF*4, AH, AL, SH, SL, wtH, wtL,
                       (c+1)*8, oc0, t);
            cpa_commit();
        }
        unsigned* bb  = dynsm + (c&1)*PJ_BUF;
        unsigned* inH = bb;
        unsigned* inL = bb + PJ_INL;
        unsigned* wH  = bb + PJ_WH;
        unsigned* wL  = bb + PJ_WL;
        unsigned aH[4], aL[4];
        aH[0] = wH[ct*40 + 16*mh + gr];      aH[1] = wH[ct*40 + 16*mh + gr + 8];
        aH[2] = wH[(ct+4)*40 + 16*mh + gr];  aH[3] = wH[(ct+4)*40 + 16*mh + gr + 8];
        aL[0] = wL[ct*40 + 16*mh + gr];      aL[1] = wL[ct*40 + 16*mh + gr + 8];
        aL[2] = wL[(ct+4)*40 + 16*mh + gr];  aL[3] = wL[(ct+4)*40 + 16*mh + gr + 8];
#pragma unroll
        for (int tt = 0; tt < 7; tt++){
            int w = nw*56 + tt*8 + gr;
            unsigned bH0 = inH[ct*232 + w];
            unsigned bH1 = inH[(ct+4)*232 + w];
            unsigned bL0 = inL[ct*232 + w];
            unsigned bL1 = inL[(ct+4)*232 + w];
            mma16816(acc[tt], aH, bH0, bH1);
            mma16816(acc[tt], aH, bL0, bL1);
            mma16816(acc[tt], aL, bH0, bH1);
        }
        // no bottom barrier: next iteration's wait0+syncthreads protects buffer reuse
    }
    const int ocA = oc0 + 16*mh + gr, ocB = ocA + 8;
    const float bA = bias[ocA], bB = bias[ocB];
    const bool evenGr = ((gr & 1) == 0);
    const int iA = (ocA >> 1)*196, iB = (ocB >> 1)*196;
#pragma unroll
    for (int tt = 0; tt < 7; tt++){
        int p0 = nw*56 + tt*8 + 2*ct, p1 = p0 + 1;
        float v00 = fmaxf(acc[tt][0] + bA, 0.f);
        float v01 = fmaxf(acc[tt][1] + bA, 0.f);
        float v10 = fmaxf(acc[tt][2] + bB, 0.f);
        float v11 = fmaxf(acc[tt][3] + bB, 0.f);
        float u00 = __shfl_xor_sync(0xffffffffu, v00, 4);
        float u01 = __shfl_xor_sync(0xffffffffu, v01, 4);
        float u10 = __shfl_xor_sync(0xffffffffu, v10, 4);
        float u11 = __shfl_xor_sync(0xffffffffu, v11, 4);
        if (evenGr){
            if (p0 < 196){
                uint2 wA = split2u(v00, u00), wB = split2u(v10, u10);
                dstH[iA+p0] = wA.x; dstL[iA+p0] = wA.y;
                dstH[iB+p0] = wB.x; dstL[iB+p0] = wB.y;
            }
            if (p1 < 196){
                uint2 wA = split2u(v01, u01), wB = split2u(v11, u11);
                dstH[iA+p1] = wA.x; dstL[iA+p1] = wA.y;
                dstH[iB+p1] = wB.x; dstL[iB+p1] = wB.y;
            }
        }
    }
}

// ---------------- persistent program kernel: 64 images x 4-CTA clusters ----------------
__global__ void __cluster_dims__(4,1,1) __launch_bounds__(256, 2)
program_kernel(const int* __restrict__ programs,
               const float* __restrict__ stem_b1, const float* __restrict__ stem_b2,
               const float* __restrict__ ub1, const float* __restrict__ ub2,
               const float* __restrict__ bbp, const float* __restrict__ bb1,
               const float* __restrict__ bb2, const float* __restrict__ cls_b)
{
    extern __shared__ unsigned dynsm[];
    const int cta = blockIdx.x;
    const int b   = cta >> 2;
    const int oc0 = (cta & 3) * 32;
    unsigned *OUTH = g_OUT_H + b*IMG2, *OUTL = g_OUT_L + b*IMG2;
    unsigned *SAVH = g_SAV_H + b*IMG2, *SAVL = g_SAV_L + b*IMG2;
    unsigned *XH   = g_X_H   + b*IMG2, *XL   = g_X_L   + b*IMG2;
    unsigned *HH   = g_H_H   + b*IMG2, *HL   = g_H_L   + b*IMG2;
    unsigned *VH   = g_V_H   + b*IMG2, *VL   = g_V_L   + b*IMG2;

    // stem
    conv3x3_mma(dynsm, g_F_H + (ull)b*512*196, g_F_L + (ull)b*512*196,
                g_stem1t, g_stem1t + STEM1_N, oc0, stem_b1,
                nullptr, nullptr, HH, HL, nullptr, nullptr, nullptr, nullptr, 512);
    csync();
    conv3x3_mma(dynsm, HH, HL, g_stem2t, g_stem2t + STEM2_N, oc0, stem_b2,
                nullptr, nullptr, VH, VL, OUTH, OUTL, SAVH, SAVL, 64);
    csync();

    // program walk (reverse token order)
    for (int tpos = LPROG-1; tpos >= 0; tpos--){
        int tok = programs[b*LPROG + tpos];
        if (tok < 4) continue;
        if (tok >= 15){                          // binary module
            int pi = tok - 15;
            proj_mma(dynsm, OUTH, OUTL, SAVH, SAVL,
                     g_bwpt + pi*128*128, g_bwpt + BWP_N + pi*128*128,
                     oc0, bbp + pi*128, XH, XL);
            csync();
            conv3x3_mma(dynsm, XH, XL,
                        g_bw1t + pi*(64*9*128), g_bw1t + BW_N + pi*(64*9*128),
                        oc0, bb1 + pi*128, nullptr, nullptr,
                        HH, HL, nullptr, nullptr, nullptr, nullptr, 64);
            csync();
            conv3x3_mma(dynsm, HH, HL,
                        g_bw2t + pi*(64*9*128), g_bw2t + BW_N + pi*(64*9*128),
                        oc0, bb2 + pi*128, XH, XL,
                        OUTH, OUTL, nullptr, nullptr, nullptr, nullptr, 64);
            csync();
        } else {                                 // scene (4) or unary (5..14)
            int pi = (tok == 4) ? 0 : tok - 4;
            const unsigned* srcH = (tok == 4) ? VH : OUTH;
            const unsigned* srcL = (tok == 4) ? VL : OUTL;
            if (tok == 4){
                for (int i = threadIdx.x; i < 16*196; i += 256){
                    int idx = (oc0 >> 1)*196 + i;
                    SAVH[idx] = OUTH[idx]; SAVL[idx] = OUTL[idx];
                }
            }
            conv3x3_mma(dynsm, srcH, srcL,
                        g_uw1t + pi*(64*9*128), g_uw1t + UW_N + pi*(64*9*128),
                        oc0, ub1 + pi*128, nullptr, nullptr,
                        HH, HL, nullptr, nullptr, nullptr, nullptr, 64);
            csync();
            conv3x3_mma(dynsm, HH, HL,
                        g_uw2t + pi*(64*9*128), g_uw2t + UW_N + pi*(64*9*128),
                        oc0, ub2 + pi*128, srcH, srcL,
                        OUTH, OUTL, nullptr, nullptr, nullptr, nullptr, 64);
            csync();
        }
    }

    // ----- fused classifier: this CTA computes cls oc [ (cta&3)*128 , +128 ) -----
    // (last loop iteration ended with csync -> OUT published across the cluster)
    {
        float* s_in = (float*)dynsm;            // [16][196]
        float* s_w  = s_in + 3136;              // [16][32]
        float* s_c  = s_w + 512;                // [32][196]
        const int t = threadIdx.x;
        const int p0 = t, p1 = t + 98;
        const bool active = (t < 98);
        const int C0 = (cta & 3)*128;

        for (int g = 0; g < 4; g++){
            int oc0c = C0 + g*32;
            ull acc0[16], acc1[16];
#pragma unroll
            for (int j = 0; j < 16; j++){ acc0[j] = 0ull; acc1[j] = 0ull; }
            for (int icg = 0; icg < 8; icg++){
                __syncthreads();
                for (int i = t; i < 8*196; i += 256){
                    int icp = i/196, p = i - icp*196;
                    unsigned vh = OUTH[(icg*8 + icp)*196 + p];
                    unsigned vl = OUTL[(icg*8 + icp)*196 + p];
                    s_in[(2*icp)*196 + p]   = lo_val2(vh, vl);
                    s_in[(2*icp+1)*196 + p] = hi_val2(vh, vl);
                }
                for (int i = t; i < 512; i += 256){
                    int oc = i & 31, ic = i >> 5;
                    s_w[ic*32 + oc] = g_clst[(icg*16 + ic)*512 + oc0c + oc];
                }
                __syncthreads();
                if (active){
#pragma unroll 4
                    for (int ic = 0; ic < 16; ic++){
                        float av = s_in[ic*196 + p0], bv = s_in[ic*196 + p1];
                        ull ap = pack2(av, av), bp = pack2(bv, bv);
#pragma unroll
                        for (int gg = 0; gg < 8; gg++){
                            ulonglong2 w2 = *reinterpret_cast<const ulonglong2*>(&s_w[ic*32 + gg*4]);
                            fma2(acc0[2*gg  ], ap, w2.x);
                            fma2(acc0[2*gg+1], ap, w2.y);
                            fma2(acc1[2*gg  ], bp, w2.x);
                            fma2(acc1[2*gg+1], bp, w2.y);
                        }
                    }
                }
            }
            __syncthreads();
            if (active){
#pragma unroll
                for (int j = 0; j < 16; j++){
                    int oc = oc0c + 2*j;
                    float a0, a1, c0, c1;
                    unpack2(acc0[j], a0, a1);
                    unpack2(acc1[j], c0, c1);
                    float bz0 = cls_b[oc], bz1 = cls_b[oc+1];
                    s_c[(2*j  )*196 + p0] = fmaxf(a0+bz0, 0.f);
                    s_c[(2*j+1)*196 + p0] = fmaxf(a1+bz1, 0.f);
                    s_c[(2*j  )*196 + p1] = fmaxf(c0+bz0, 0.f);
                    s_c[(2*j+1)*196 + p1] = fmaxf(c1+bz1, 0.f);
                }
            }
            __syncthreads();
            for (int i = t; i < 32*49; i += 256){
                int ocl = i/49, cell = i - ocl*49;
                int py = cell/7, px = cell - py*7;
                int base = 28*py + 2*px;
                float m = fmaxf(fmaxf(s_c[ocl*196 + base], s_c[ocl*196 + base+1]),
                                fmaxf(s_c[ocl*196 + base+14], s_c[ocl*196 + base+15]));
                g_FLAT[b*25088 + (oc0c + ocl)*49 + cell] = m;
            }
        }
    }
}

// ---------------- fc1 via bf16-split tensor cores ----------------
__global__ void fc1_kernel(const float* __restrict__ w){
    const int n0 = blockIdx.x*64;
    const int k0 = blockIdx.y*1568;
    __shared__ unsigned sAh[16][72], sAl[16][72], sBh[16][72], sBl[16][72];
    const int t = threadIdx.x;
    const int lane = t & 31, wid = t >> 5;
    const int gr = lane >> 2, ct = lane & 3;
    const int mt = wid >> 1, nh = wid & 1;
    float acc[4][4] = {};

    for (int kk = 0; kk < 1568; kk += 32){
        __syncthreads();
        for (int i = t; i < 1024; i += 256){
            int kp = i & 15, m = i >> 4;
            const float* a = g_FLAT + m*25088 + k0 + kk + 2*kp;
            unsigned h, l; split2(a[0], a[1], h, l);
            sAh[kp][m] = h; sAl[kp][m] = l;
            const float* bptr = w + (ull)(n0 + m)*25088 + k0 + kk + 2*kp;
            split2(bptr[0], bptr[1], h, l);
            sBh[kp][m] = h; sBl[kp][m] = l;
        }
        __syncthreads();
#pragma unroll
        for (int ks = 0; ks < 2; ks++){
            const int kp0 = ks*8;
            unsigned aH[4], aL[4];
            aH[0] = sAh[kp0+ct][mt*16+gr];     aH[1] = sAh[kp0+ct][mt*16+gr+8];
            aH[2] = sAh[kp0+ct+4][mt*16+gr];   aH[3] = sAh[kp0+ct+4][mt*16+gr+8];
            aL[0] = sAl[kp0+ct][mt*16+gr];     aL[1] = sAl[kp0+ct][mt*16+gr+8];
            aL[2] = sAl[kp0+ct+4][mt*16+gr];   aL[3] = sAl[kp0+ct+4][mt*16+gr+8];
#pragma unroll
            for (int tile = 0; tile < 4; tile++){
                int n = nh*32 + tile*8 + gr;
                unsigned bH0 = sBh[kp0+ct][n],   bH1 = sBh[kp0+ct+4][n];
                unsigned bL0 = sBl[kp0+ct][n],   bL1 = sBl[kp0+ct+4][n];
                mma16816(acc[tile], aH, bH0, bH1);
                mma16816(acc[tile], aH, bL0, bL1);
                mma16816(acc[tile], aL, bH0, bH1);
            }
        }
    }
#pragma unroll
    for (int tile = 0; tile < 4; tile++){
        int m = mt*16 + gr;
        int n = n0 + nh*32 + tile*8 + 2*ct;
        atomicAdd(&g_FC1[m*1024 + n],       acc[tile][0]);
        atomicAdd(&g_FC1[m*1024 + n + 1],   acc[tile][1]);
        atomicAdd(&g_FC1[(m+8)*1024 + n],   acc[tile][2]);
        atomicAdd(&g_FC1[(m+8)*1024 + n+1], acc[tile][3]);
    }
}

// ---------------- fc2 ----------------
__global__ void fc2_kernel(const float* __restrict__ fc1_b, const float* __restrict__ w2,
                           const float* __restrict__ b2, float* __restrict__ out){
    int b = blockIdx.x;
    const int t = threadIdx.x;
    int n2 = t >> 3, kl = t & 7;
    float acc = 0.f;
    for (int k = kl; k < 1024; k += 8)
        acc += fmaxf(g_FC1[b*1024 + k] + fc1_b[k], 0.f) * w2[n2*1024 + k];
    __shared__ float red[256];
    red[t] = acc;
    __syncthreads();
    if (kl == 0){
        float s = red[t];
#pragma unroll
        for (int q = 1; q < 8; q++) s += red[t+q];
        out[b*32 + n2] = s + b2[n2];
    }
}

// ---------------- launch ----------------
extern "C" void kernel_launch(void* const* d_in, const int* in_sizes, int n_in,
                              void* d_out, int out_size){
    const float* feats    = (const float*)d_in[0];
    const int*   programs = (const int*)  d_in[1];
    const float* stem_w1  = (const float*)d_in[2];
    const float* stem_b1  = (const float*)d_in[3];
    const float* stem_w2  = (const float*)d_in[4];
    const float* stem_b2  = (const float*)d_in[5];
    const float* uw1      = (const float*)d_in[6];
    const float* ub1      = (const float*)d_in[7];
    const float* uw2      = (const float*)d_in[8];
    const float* ub2      = (const float*)d_in[9];
    const float* bwp      = (const float*)d_in[10];
    const float* bbp      = (const float*)d_in[11];
    const float* bw1      = (const float*)d_in[12];
    const float* bb1      = (const float*)d_in[13];
    const float* bw2      = (const float*)d_in[14];
    const float* bb2      = (const float*)d_in[15];
    const float* cls_w    = (const float*)d_in[16];
    const float* cls_b    = (const float*)d_in[17];
    const float* fc1_w    = (const float*)d_in[18];
    const float* fc1_b    = (const float*)d_in[19];
    const float* fc2_w    = (const float*)d_in[20];
    const float* fc2_b    = (const float*)d_in[21];
    float* out = (float*)d_out;

    static bool attr_set = false;
    if (!attr_set){
        cudaFuncSetAttribute(program_kernel,
                             cudaFuncAttributeMaxDynamicSharedMemorySize, DYN_SMEM);
        attr_set = true;
    }

    tr1<<<1024, 256>>>(stem_w1, uw1, feats);
    tr2<<<1024, 256>>>(uw2, bw1, bw2, feats);
    tr3<<<512,  256>>>(stem_w2, bwp, cls_w);

    program_kernel<<<BB*4, 256, DYN_SMEM>>>(programs, stem_b1, stem_b2,
                                            ub1, ub2, bbp, bb1, bb2, cls_b);

    fc1_kernel<<<dim3(16, 16), 256>>>(fc1_w);
    fc2_kernel<<<BB, 256>>>(fc1_b, fc2_w, fc2_b, out);
}